// round 10
// baseline (speedup 1.0000x reference)
#include <cuda_runtime.h>
#include <math.h>

// Shapes: [B=4, C=1, D=128, H=192, W=192]; dsc: [4,1,8,12,12] = 4608
#define BB 4
#define DD 128
#define HH 192
#define WW 192
#define SD (HH*WW)          // 36864  (D stride, elements)
#define SH (WW)             // 192    (H stride, elements)
#define NTOT (BB*DD*HH*WW)  // 18,874,368
#define NDSC 4608

#define W2 (WW/2)           // 96 float2 groups per W line
#define H2 (HH/2)           // 96 row pairs
#define DCH 16              // d-planes per thread (rolling window)
#define NCHUNK (DD/DCH)     // 8
#define NTHREADS (BB*H2*W2*NCHUNK)   // 294,912
#define TPB 256
#define NBLK (NTHREADS/TPB)          // 1152 (exact)

__device__ double g_part[NBLK][2];
__device__ float  g_bce;
__device__ int    g_count;   // zero-init; last block restores to 0

__device__ __forceinline__ float2 ld2(const float* __restrict__ p) {
    return *reinterpret_cast<const float2*>(p);
}

// One D-plane step. NO = next-plane offset (compile-time SD or 0).
// ACCD = accumulator for unscaled D-axis terms (0.25x applied at end, or 1x for edges).
#define STEP(NO, ACCD)                                                        \
{                                                                             \
    float2 y0n = ld2(y0 + (NO));                                              \
    float2 y1n = ld2(y0 + SH + (NO));                                         \
    float2 p0n = ld2(p0 + (NO));                                              \
    float2 p1n = ld2(p0 + SH + (NO));                                         \
    float2 yhm = h0e ? y0c : ld2(y0 - SH);                                    \
    float2 phm = h0e ? p0c : ld2(p0 - SH);                                    \
    float2 yhp = h1e ? y1c : ld2(y0 + 2 * SH);                                \
    float2 php = h1e ? p1c : ld2(p0 + 2 * SH);                                \
    float y0l = __shfl_up_sync(0xFFFFFFFFu, y0c.y, 1);                        \
    float y1l = __shfl_up_sync(0xFFFFFFFFu, y1c.y, 1);                        \
    float p0l = __shfl_up_sync(0xFFFFFFFFu, p0c.y, 1);                        \
    float p1l = __shfl_up_sync(0xFFFFFFFFu, p1c.y, 1);                        \
    float y0r = __shfl_down_sync(0xFFFFFFFFu, y0c.x, 1);                      \
    float y1r = __shfl_down_sync(0xFFFFFFFFu, y1c.x, 1);                      \
    float p0r = __shfl_down_sync(0xFFFFFFFFu, p0c.x, 1);                      \
    float p1r = __shfl_down_sync(0xFFFFFFFFu, p1c.x, 1);                      \
    if (lload) {                                                              \
        y0l = y0[-1]; y1l = y0[SH - 1];                                       \
        p0l = p0[-1]; p1l = p0[SH - 1];                                       \
    }                                                                         \
    if (rload) {                                                              \
        y0r = y0[2]; y1r = y0[SH + 2];                                        \
        p0r = p0[2]; p1r = p0[SH + 2];                                        \
    }                                                                         \
    if (w0e) { y0l = y0c.x; y1l = y1c.x; p0l = p0c.x; p1l = p1c.x; }          \
    if (w1e) { y0r = y0c.y; y1r = y1c.y; p0r = p0c.y; p1r = p1c.y; }          \
    l1_acc += fabsf(y0c.x - p0c.x) + fabsf(y0c.y - p0c.y)                     \
            + fabsf(y1c.x - p1c.x) + fabsf(y1c.y - p1c.y);                    \
    float tt;                                                                 \
    tt = fabsf(y0n.x - y0p.x) - fabsf(p0n.x - p0p.x); ACCD = fmaf(tt, tt, ACCD); \
    tt = fabsf(y0n.y - y0p.y) - fabsf(p0n.y - p0p.y); ACCD = fmaf(tt, tt, ACCD); \
    tt = fabsf(y1n.x - y1p.x) - fabsf(p1n.x - p1p.x); ACCD = fmaf(tt, tt, ACCD); \
    tt = fabsf(y1n.y - y1p.y) - fabsf(p1n.y - p1p.y); ACCD = fmaf(tt, tt, ACCD); \
    tt = fabsf(y1c.x - yhm.x) - fabsf(p1c.x - phm.x); gd_acc = fmaf(hs0 * tt, tt, gd_acc); \
    tt = fabsf(y1c.y - yhm.y) - fabsf(p1c.y - phm.y); gd_acc = fmaf(hs0 * tt, tt, gd_acc); \
    tt = fabsf(yhp.x - y0c.x) - fabsf(php.x - p0c.x); gd_acc = fmaf(hs1 * tt, tt, gd_acc); \
    tt = fabsf(yhp.y - y0c.y) - fabsf(php.y - p0c.y); gd_acc = fmaf(hs1 * tt, tt, gd_acc); \
    tt = fabsf(y0c.y - y0l) - fabsf(p0c.y - p0l);     gd_acc = fmaf(wl2 * tt, tt, gd_acc); \
    tt = fabsf(y0r - y0c.x) - fabsf(p0r - p0c.x);     gd_acc = fmaf(wr2 * tt, tt, gd_acc); \
    tt = fabsf(y1c.y - y1l) - fabsf(p1c.y - p1l);     gd_acc = fmaf(wl2 * tt, tt, gd_acc); \
    tt = fabsf(y1r - y1c.x) - fabsf(p1r - p1c.x);     gd_acc = fmaf(wr2 * tt, tt, gd_acc); \
    y0p = y0c; y0c = y0n;                                                     \
    y1p = y1c; y1c = y1n;                                                     \
    p0p = p0c; p0c = p0n;                                                     \
    p1p = p1c; p1c = p1n;                                                     \
    y0 += SD; p0 += SD;                                                       \
}

__global__ void __launch_bounds__(TPB, 5)   // target <=48 regs -> 5 blocks/SM
vol_kernel(const float* __restrict__ predicts,
           const float* __restrict__ y_data,
           const float* __restrict__ dsc_fake,
           const float* __restrict__ zeros,
           float* __restrict__ out)
{
    __shared__ float s_a[8];
    __shared__ float s_b[8];
    __shared__ bool  s_last;
    const int lane = threadIdx.x & 31;
    const int wid  = threadIdx.x >> 5;

    // ---- Block 0: BCE in parallel with everyone's main work ----
    if (blockIdx.x == 0) {
        float s = 0.0f;
        for (int i = threadIdx.x; i < NDSC; i += TPB) {
            float x = dsc_fake[i];
            float z = zeros[i];
            s += fmaxf(x, 0.0f) - x * z + log1pf(expf(-fabsf(x)));
        }
        #pragma unroll
        for (int off = 16; off > 0; off >>= 1)
            s += __shfl_down_sync(0xFFFFFFFFu, s, off);
        if (lane == 0) s_a[wid] = s;
        __syncthreads();
        if (wid == 0) {
            s = (lane < 8) ? s_a[lane] : 0.0f;
            #pragma unroll
            for (int off = 4; off > 0; off >>= 1)
                s += __shfl_down_sync(0xFFFFFFFFu, s, off);
            if (lane == 0) g_bce = s;
        }
        __syncthreads();
    }

    // ---- Index decode: thread owns rows (h0, h0+1), cols (w0, w0+1) ----
    const int tid = blockIdx.x * TPB + threadIdx.x;   // exact fit
    const int w2 = tid % W2;
    int t  = tid / W2;
    const int h2 = t % H2;
    t /= H2;
    const int dc = t % NCHUNK;   // warp-uniform (warps never straddle w-rows: 96 = 3*32)
    const int b  = t / NCHUNK;

    const int h0 = 2 * h2;
    const int w0 = 2 * w2;
    const int d0 = dc * DCH;

    const long ofs = ((long)(b * DD + d0) * HH + h0) * WW + w0;
    const float* __restrict__ y0 = y_data   + ofs;
    const float* __restrict__ p0 = predicts + ofs;

    const bool h0e = (h0 == 0);
    const bool h1e = (h2 == H2 - 1);
    const bool w0e = (w2 == 0);
    const bool w1e = (w2 == W2 - 1);
    const float hs0 = h0e ? 1.0f : 0.25f;
    const float hs1 = h1e ? 1.0f : 0.25f;
    const float wl2 = w0e ? 1.0f : 0.25f;
    const float wr2 = w1e ? 1.0f : 0.25f;
    const bool lload = (lane == 0)  && !w0e;
    const bool rload = (lane == 31) && !w1e;

    float2 y0c = ld2(y0);
    float2 y1c = ld2(y0 + SH);
    float2 p0c = ld2(p0);
    float2 p1c = ld2(p0 + SH);
    float2 y0p = (d0 > 0) ? ld2(y0 - SD)      : y0c;
    float2 y1p = (d0 > 0) ? ld2(y0 + SH - SD) : y1c;
    float2 p0p = (d0 > 0) ? ld2(p0 - SD)      : p0c;
    float2 p1p = (d0 > 0) ? ld2(p0 + SH - SD) : p1c;

    float l1_acc = 0.0f;
    float gd_acc = 0.0f;    // H/W terms (scale folded per-term)
    float gdD25  = 0.0f;    // interior D terms (x0.25 at end)
    float gdD1   = 0.0f;    // edge D terms (x1.0)

    // Peeled d-edge iterations (warp-uniform branches) -> interior loop uses
    // immediate +SD offsets and no per-iter d/scale computation.
    int nInterior = DCH;
    if (dc == 0) { STEP(SD, gdD1); nInterior--; }       // d = 0 (one-sided)
    const bool lastChunk = (dc == NCHUNK - 1);
    if (lastChunk) nInterior--;                          // reserve d = 127

    #pragma unroll 2
    for (int i = 0; i < nInterior; i++) { STEP(SD, gdD25); }

    if (lastChunk) { STEP(0, gdD1); }                    // d = 127 (one-sided)

    gd_acc += 0.25f * gdD25 + gdD1;

    // ---- Block reduction ----
    #pragma unroll
    for (int off = 16; off > 0; off >>= 1) {
        l1_acc += __shfl_down_sync(0xFFFFFFFFu, l1_acc, off);
        gd_acc += __shfl_down_sync(0xFFFFFFFFu, gd_acc, off);
    }
    if (lane == 0) { s_a[wid] = l1_acc; s_b[wid] = gd_acc; }
    __syncthreads();

    if (wid == 0) {
        l1_acc = (lane < 8) ? s_a[lane] : 0.0f;
        gd_acc = (lane < 8) ? s_b[lane] : 0.0f;
        #pragma unroll
        for (int off = 4; off > 0; off >>= 1) {
            l1_acc += __shfl_down_sync(0xFFFFFFFFu, l1_acc, off);
            gd_acc += __shfl_down_sync(0xFFFFFFFFu, gd_acc, off);
        }
        if (lane == 0) {
            g_part[blockIdx.x][0] = (double)l1_acc;
            g_part[blockIdx.x][1] = (double)gd_acc;
        }
    }

    // ---- Last-block final reduction ----
    if (threadIdx.x == 0) {
        __threadfence();
        int prev = atomicAdd(&g_count, 1);
        s_last = (prev == NBLK - 1);
    }
    __syncthreads();

    if (s_last) {
        double l1d = 0.0, gdd = 0.0;
        for (int i = threadIdx.x; i < NBLK; i += TPB) {
            l1d += g_part[i][0];
            gdd += g_part[i][1];
        }
        #pragma unroll
        for (int off = 16; off > 0; off >>= 1) {
            l1d += __shfl_down_sync(0xFFFFFFFFu, l1d, off);
            gdd += __shfl_down_sync(0xFFFFFFFFu, gdd, off);
        }
        __shared__ double sh_l1[8];
        __shared__ double sh_gd[8];
        if (lane == 0) { sh_l1[wid] = l1d; sh_gd[wid] = gdd; }
        __syncthreads();
        if (wid == 0) {
            l1d = (lane < 8) ? sh_l1[lane] : 0.0;
            gdd = (lane < 8) ? sh_gd[lane] : 0.0;
            #pragma unroll
            for (int off = 4; off > 0; off >>= 1) {
                l1d += __shfl_down_sync(0xFFFFFFFFu, l1d, off);
                gdd += __shfl_down_sync(0xFFFFFFFFu, gdd, off);
            }
            if (lane == 0) {
                double bce = (double)g_bce / (double)NDSC;
                double l1m = l1d / (double)NTOT;
                double gdm = gdd / (double)NTOT;
                out[0] = (float)(bce + 100.0 * l1m + 100.0 * gdm);
                g_count = 0;   // restore for deterministic graph replay
            }
        }
    }
}

extern "C" void kernel_launch(void* const* d_in, const int* in_sizes, int n_in,
                              void* d_out, int out_size)
{
    const float* dsc_fake = (const float*)d_in[0];
    const float* predicts = (const float*)d_in[1];
    const float* y_data   = (const float*)d_in[2];
    const float* zeros    = (const float*)d_in[3];
    float* out = (float*)d_out;

    vol_kernel<<<NBLK, TPB>>>(predicts, y_data, dsc_fake, zeros, out);
}

// round 13
// speedup vs baseline: 2.1348x; 2.1348x over previous
#include <cuda_runtime.h>
#include <math.h>

// Shapes: [B=4, C=1, D=128, H=192, W=192]; dsc: [4,1,8,12,12] = 4608
#define BB 4
#define DD 128
#define HH 192
#define WW 192
#define SD (HH*WW)          // 36864  (D stride, elements)
#define SH (WW)             // 192    (H stride, elements)
#define NTOT (BB*DD*HH*WW)  // 18,874,368
#define NDSC 4608

#define W2 (WW/2)           // 96 float2 groups per W line
#define H2 (HH/2)           // 96 row pairs
#define DCH 16              // d-planes per thread (rolling window)
#define NCHUNK (DD/DCH)     // 8
#define NTHREADS (BB*H2*W2*NCHUNK)   // 294,912
#define TPB 256
#define NBLK (NTHREADS/TPB)          // 1152 (exact)

__device__ double g_part[NBLK][2];
__device__ float  g_bce;
__device__ int    g_count;   // zero-init; last block restores to 0

__device__ __forceinline__ float2 ld2(const float* __restrict__ p) {
    return *reinterpret_cast<const float2*>(p);
}

// One D-plane step. NO = next-plane offset (compile-time SD or 0).
// ACCD = accumulator for unscaled D-axis terms (0.25x applied at end, or 1x for edges).
#define STEP(NO, ACCD)                                                        \
{                                                                             \
    float2 y0n = ld2(y0 + (NO));                                              \
    float2 y1n = ld2(y0 + SH + (NO));                                         \
    float2 p0n = ld2(p0 + (NO));                                              \
    float2 p1n = ld2(p0 + SH + (NO));                                         \
    float2 yhm = h0e ? y0c : ld2(y0 - SH);                                    \
    float2 phm = h0e ? p0c : ld2(p0 - SH);                                    \
    float2 yhp = h1e ? y1c : ld2(y0 + 2 * SH);                                \
    float2 php = h1e ? p1c : ld2(p0 + 2 * SH);                                \
    float y0l = __shfl_up_sync(0xFFFFFFFFu, y0c.y, 1);                        \
    float y1l = __shfl_up_sync(0xFFFFFFFFu, y1c.y, 1);                        \
    float p0l = __shfl_up_sync(0xFFFFFFFFu, p0c.y, 1);                        \
    float p1l = __shfl_up_sync(0xFFFFFFFFu, p1c.y, 1);                        \
    float y0r = __shfl_down_sync(0xFFFFFFFFu, y0c.x, 1);                      \
    float y1r = __shfl_down_sync(0xFFFFFFFFu, y1c.x, 1);                      \
    float p0r = __shfl_down_sync(0xFFFFFFFFu, p0c.x, 1);                      \
    float p1r = __shfl_down_sync(0xFFFFFFFFu, p1c.x, 1);                      \
    if (lload) {                                                              \
        y0l = y0[-1]; y1l = y0[SH - 1];                                       \
        p0l = p0[-1]; p1l = p0[SH - 1];                                       \
    }                                                                         \
    if (rload) {                                                              \
        y0r = y0[2]; y1r = y0[SH + 2];                                        \
        p0r = p0[2]; p1r = p0[SH + 2];                                        \
    }                                                                         \
    if (w0e) { y0l = y0c.x; y1l = y1c.x; p0l = p0c.x; p1l = p1c.x; }          \
    if (w1e) { y0r = y0c.y; y1r = y1c.y; p0r = p0c.y; p1r = p1c.y; }          \
    l1_acc += fabsf(y0c.x - p0c.x) + fabsf(y0c.y - p0c.y)                     \
            + fabsf(y1c.x - p1c.x) + fabsf(y1c.y - p1c.y);                    \
    float tt;                                                                 \
    tt = fabsf(y0n.x - y0p.x) - fabsf(p0n.x - p0p.x); ACCD = fmaf(tt, tt, ACCD); \
    tt = fabsf(y0n.y - y0p.y) - fabsf(p0n.y - p0p.y); ACCD = fmaf(tt, tt, ACCD); \
    tt = fabsf(y1n.x - y1p.x) - fabsf(p1n.x - p1p.x); ACCD = fmaf(tt, tt, ACCD); \
    tt = fabsf(y1n.y - y1p.y) - fabsf(p1n.y - p1p.y); ACCD = fmaf(tt, tt, ACCD); \
    tt = fabsf(y1c.x - yhm.x) - fabsf(p1c.x - phm.x); gd_acc = fmaf(hs0 * tt, tt, gd_acc); \
    tt = fabsf(y1c.y - yhm.y) - fabsf(p1c.y - phm.y); gd_acc = fmaf(hs0 * tt, tt, gd_acc); \
    tt = fabsf(yhp.x - y0c.x) - fabsf(php.x - p0c.x); gd_acc = fmaf(hs1 * tt, tt, gd_acc); \
    tt = fabsf(yhp.y - y0c.y) - fabsf(php.y - p0c.y); gd_acc = fmaf(hs1 * tt, tt, gd_acc); \
    tt = fabsf(y0c.y - y0l) - fabsf(p0c.y - p0l);     gd_acc = fmaf(wl2 * tt, tt, gd_acc); \
    tt = fabsf(y0r - y0c.x) - fabsf(p0r - p0c.x);     gd_acc = fmaf(wr2 * tt, tt, gd_acc); \
    tt = fabsf(y1c.y - y1l) - fabsf(p1c.y - p1l);     gd_acc = fmaf(wl2 * tt, tt, gd_acc); \
    tt = fabsf(y1r - y1c.x) - fabsf(p1r - p1c.x);     gd_acc = fmaf(wr2 * tt, tt, gd_acc); \
    y0p = y0c; y0c = y0n;                                                     \
    y1p = y1c; y1c = y1n;                                                     \
    p0p = p0c; p0c = p0n;                                                     \
    p1p = p1c; p1c = p1n;                                                     \
    y0 += SD; p0 += SD;                                                       \
}

__global__ void __launch_bounds__(TPB, 4)   // 64 regs: known-good, no spills
vol_kernel(const float* __restrict__ predicts,
           const float* __restrict__ y_data,
           const float* __restrict__ dsc_fake,
           const float* __restrict__ zeros,
           float* __restrict__ out)
{
    __shared__ float s_a[8];
    __shared__ float s_b[8];
    __shared__ bool  s_last;
    const int lane = threadIdx.x & 31;
    const int wid  = threadIdx.x >> 5;

    // ---- Block 0: BCE in parallel with everyone's main work ----
    if (blockIdx.x == 0) {
        float s = 0.0f;
        for (int i = threadIdx.x; i < NDSC; i += TPB) {
            float x = dsc_fake[i];
            float z = zeros[i];
            s += fmaxf(x, 0.0f) - x * z + log1pf(expf(-fabsf(x)));
        }
        #pragma unroll
        for (int off = 16; off > 0; off >>= 1)
            s += __shfl_down_sync(0xFFFFFFFFu, s, off);
        if (lane == 0) s_a[wid] = s;
        __syncthreads();
        if (wid == 0) {
            s = (lane < 8) ? s_a[lane] : 0.0f;
            #pragma unroll
            for (int off = 4; off > 0; off >>= 1)
                s += __shfl_down_sync(0xFFFFFFFFu, s, off);
            if (lane == 0) g_bce = s;
        }
        __syncthreads();
    }

    // ---- Index decode: thread owns rows (h0, h0+1), cols (w0, w0+1) ----
    const int tid = blockIdx.x * TPB + threadIdx.x;   // exact fit
    const int w2 = tid % W2;
    int t  = tid / W2;
    const int h2 = t % H2;
    t /= H2;
    const int dc = t % NCHUNK;   // warp-uniform (warps never straddle w-rows: 96 = 3*32)
    const int b  = t / NCHUNK;

    const int h0 = 2 * h2;
    const int w0 = 2 * w2;
    const int d0 = dc * DCH;

    const long ofs = ((long)(b * DD + d0) * HH + h0) * WW + w0;
    const float* __restrict__ y0 = y_data   + ofs;
    const float* __restrict__ p0 = predicts + ofs;

    const bool h0e = (h0 == 0);
    const bool h1e = (h2 == H2 - 1);
    const bool w0e = (w2 == 0);
    const bool w1e = (w2 == W2 - 1);
    const float hs0 = h0e ? 1.0f : 0.25f;
    const float hs1 = h1e ? 1.0f : 0.25f;
    const float wl2 = w0e ? 1.0f : 0.25f;
    const float wr2 = w1e ? 1.0f : 0.25f;
    const bool lload = (lane == 0)  && !w0e;
    const bool rload = (lane == 31) && !w1e;

    float2 y0c = ld2(y0);
    float2 y1c = ld2(y0 + SH);
    float2 p0c = ld2(p0);
    float2 p1c = ld2(p0 + SH);
    float2 y0p = (d0 > 0) ? ld2(y0 - SD)      : y0c;
    float2 y1p = (d0 > 0) ? ld2(y0 + SH - SD) : y1c;
    float2 p0p = (d0 > 0) ? ld2(p0 - SD)      : p0c;
    float2 p1p = (d0 > 0) ? ld2(p0 + SH - SD) : p1c;

    float l1_acc = 0.0f;
    float gd_acc = 0.0f;    // H/W terms (scale folded per-term)
    float gdD25  = 0.0f;    // interior D terms (x0.25 at end)
    float gdD1   = 0.0f;    // edge D terms (x1.0)

    // Peeled d-edge iterations (warp-uniform branches) -> interior loop uses
    // immediate +SD offsets and no per-iter d/scale computation.
    int nInterior = DCH;
    if (dc == 0) { STEP(SD, gdD1); nInterior--; }       // d = 0 (one-sided)
    const bool lastChunk = (dc == NCHUNK - 1);
    if (lastChunk) nInterior--;                          // reserve d = 127

    #pragma unroll 2
    for (int i = 0; i < nInterior; i++) { STEP(SD, gdD25); }

    if (lastChunk) { STEP(0, gdD1); }                    // d = 127 (one-sided)

    gd_acc += 0.25f * gdD25 + gdD1;

    // ---- Block reduction ----
    #pragma unroll
    for (int off = 16; off > 0; off >>= 1) {
        l1_acc += __shfl_down_sync(0xFFFFFFFFu, l1_acc, off);
        gd_acc += __shfl_down_sync(0xFFFFFFFFu, gd_acc, off);
    }
    if (lane == 0) { s_a[wid] = l1_acc; s_b[wid] = gd_acc; }
    __syncthreads();

    if (wid == 0) {
        l1_acc = (lane < 8) ? s_a[lane] : 0.0f;
        gd_acc = (lane < 8) ? s_b[lane] : 0.0f;
        #pragma unroll
        for (int off = 4; off > 0; off >>= 1) {
            l1_acc += __shfl_down_sync(0xFFFFFFFFu, l1_acc, off);
            gd_acc += __shfl_down_sync(0xFFFFFFFFu, gd_acc, off);
        }
        if (lane == 0) {
            g_part[blockIdx.x][0] = (double)l1_acc;
            g_part[blockIdx.x][1] = (double)gd_acc;
        }
    }

    // ---- Last-block final reduction ----
    if (threadIdx.x == 0) {
        __threadfence();
        int prev = atomicAdd(&g_count, 1);
        s_last = (prev == NBLK - 1);
    }
    __syncthreads();

    if (s_last) {
        double l1d = 0.0, gdd = 0.0;
        for (int i = threadIdx.x; i < NBLK; i += TPB) {
            l1d += g_part[i][0];
            gdd += g_part[i][1];
        }
        #pragma unroll
        for (int off = 16; off > 0; off >>= 1) {
            l1d += __shfl_down_sync(0xFFFFFFFFu, l1d, off);
            gdd += __shfl_down_sync(0xFFFFFFFFu, gdd, off);
        }
        __shared__ double sh_l1[8];
        __shared__ double sh_gd[8];
        if (lane == 0) { sh_l1[wid] = l1d; sh_gd[wid] = gdd; }
        __syncthreads();
        if (wid == 0) {
            l1d = (lane < 8) ? sh_l1[lane] : 0.0;
            gdd = (lane < 8) ? sh_gd[lane] : 0.0;
            #pragma unroll
            for (int off = 4; off > 0; off >>= 1) {
                l1d += __shfl_down_sync(0xFFFFFFFFu, l1d, off);
                gdd += __shfl_down_sync(0xFFFFFFFFu, gdd, off);
            }
            if (lane == 0) {
                double bce = (double)g_bce / (double)NDSC;
                double l1m = l1d / (double)NTOT;
                double gdm = gdd / (double)NTOT;
                out[0] = (float)(bce + 100.0 * l1m + 100.0 * gdm);
                g_count = 0;   // restore for deterministic graph replay
            }
        }
    }
}

extern "C" void kernel_launch(void* const* d_in, const int* in_sizes, int n_in,
                              void* d_out, int out_size)
{
    const float* dsc_fake = (const float*)d_in[0];
    const float* predicts = (const float*)d_in[1];
    const float* y_data   = (const float*)d_in[2];
    const float* zeros    = (const float*)d_in[3];
    float* out = (float*)d_out;

    vol_kernel<<<NBLK, TPB>>>(predicts, y_data, dsc_fake, zeros, out);
}